// round 2
// baseline (speedup 1.0000x reference)
#include <cuda_runtime.h>
#include <cstdint>

// STModel: GCN scatter-agg (scalar features x 48 time-batch slots) + folded
// temporal conv / relu / pool / linear epilogue.
//
// Pipeline (all linear ops before ReLU are folded):
//   deg[d]  = 1 + sum_{e: dst=d} w[e]          -> dinv = rsqrt(deg)
//   agg[n,bt] = sum_e norm_e * x[bt, src_e]  (+ dinv[n]^2 * x[bt,n] self-loop,
//                                             folded into epilogue)
//   A[o,k] = sum_i conv_w[o,i,k]*gcn_w[i];  C[o,k] = sum_i conv_w[o,i,k]*gcn_b[i]
//   z[o,t] = conv_b[o] + sum_{valid k} (A[o,k]*s[t+k-1] + C[o,k])
//   out[b,n] = lin_b + (1/12) * sum_{t,o} lin_w[o] * relu(z[o,t])

#define MAXN 50000
#define NB 4
#define NT 12
#define NBT 48
#define NH 32

__device__ float  g_dinv[MAXN];        // deg accumulator, then dinv in place
__device__ float4 g_xt[MAXN * 12];     // x transposed: [N][48] as float4[N][12]
__device__ float4 g_agg[MAXN * 12];    // aggregate:    [N][48] as float4[N][12]
__device__ float  g_A[3 * NH];         // A[k][o]
__device__ float  g_C[3 * NH];         // C[k][o]
__device__ unsigned g_oddor;           // !=0  => edge_index is int32; ==0 => int64

// ---------------------------------------------------------------------------
__global__ void k_init(int n) {
    int i = blockIdx.x * blockDim.x + threadIdx.x;
    if (i < n * 12) g_agg[i] = make_float4(0.f, 0.f, 0.f, 0.f);
    if (i < n) g_dinv[i] = 1.0f;       // self-loop weight preloaded into deg
    if (i == 0) g_oddor = 0u;
}

// Detect edge_index dtype: scan odd 32-bit words of the FIRST 2E words (safe
// for both int32 [2E words total... 2E = full buffer] and int64 [first E
// values' (lo,hi) pairs]). int64 => all hi words zero => OR == 0.
__global__ void k_detect(const unsigned* __restrict__ w, int e) {
    unsigned acc = 0;
    for (int i = blockIdx.x * blockDim.x + threadIdx.x; i < e;
         i += gridDim.x * blockDim.x)
        acc |= w[2 * i + 1];
#pragma unroll
    for (int m = 16; m; m >>= 1) acc |= __shfl_xor_sync(0xffffffffu, acc, m);
    if ((threadIdx.x & 31) == 0 && acc) atomicOr(&g_oddor, acc);
}

__global__ void k_deg(const void* __restrict__ ei, const float* __restrict__ ew,
                      int e) {
    int i = blockIdx.x * blockDim.x + threadIdx.x;
    if (i >= e) return;
    int d;
    if (g_oddor) {
        d = ((const int*)ei)[e + i];
    } else {
        d = (int)((const long long*)ei)[e + i];
    }
    atomicAdd(&g_dinv[d], ew[i]);
}

__global__ void k_rsqrt(int n) {
    int i = blockIdx.x * blockDim.x + threadIdx.x;
    if (i < n) {
        float dg = g_dinv[i];
        g_dinv[i] = (dg > 0.f) ? rsqrtf(dg) : 0.f;
    }
}

// x [48, N] -> g_xt [N][48] (float4-packed)
__global__ void k_trans(const float* __restrict__ x, int n) {
    int node = blockIdx.x * blockDim.x + threadIdx.x;
    if (node >= n) return;
    float v[NBT];
#pragma unroll
    for (int bt = 0; bt < NBT; bt++) v[bt] = x[bt * n + node];
#pragma unroll
    for (int j = 0; j < 12; j++)
        g_xt[node * 12 + j] =
            make_float4(v[4 * j], v[4 * j + 1], v[4 * j + 2], v[4 * j + 3]);
}

// One thread per edge: 48 scaled scatter-adds into agg[dst].
__global__ void k_agg(const void* __restrict__ ei, const float* __restrict__ ew,
                      int e) {
    int i = blockIdx.x * blockDim.x + threadIdx.x;
    if (i >= e) return;
    int s, d;
    if (g_oddor) {
        const int* p = (const int*)ei;
        s = p[i];
        d = p[e + i];
    } else {
        const long long* p = (const long long*)ei;
        s = (int)p[i];
        d = (int)p[e + i];
    }
    float norm = g_dinv[s] * ew[i] * g_dinv[d];
    float* ap = (float*)&g_agg[d * 12];
#pragma unroll
    for (int j = 0; j < 12; j++) {
        float4 v = g_xt[s * 12 + j];
        atomicAdd(ap + 4 * j + 0, v.x * norm);
        atomicAdd(ap + 4 * j + 1, v.y * norm);
        atomicAdd(ap + 4 * j + 2, v.z * norm);
        atomicAdd(ap + 4 * j + 3, v.w * norm);
    }
}

__global__ void k_prep(const float* __restrict__ cw, const float* __restrict__ gw,
                       const float* __restrict__ gb) {
    int t = threadIdx.x;
    if (t >= 96) return;
    int o = t / 3, k = t % 3;
    float a = 0.f, c = 0.f;
    for (int i = 0; i < NH; i++) {
        float w = cw[o * (NH * 3) + i * 3 + k];
        a += w * gw[i];
        c += w * gb[i];
    }
    g_A[k * NH + o] = a;
    g_C[k * NH + o] = c;
}

__global__ void __launch_bounds__(128) k_out(const float* __restrict__ cb,
                                             const float* __restrict__ lw,
                                             const float* __restrict__ lb,
                                             float* __restrict__ out, int n) {
    __shared__ float sA0[NH], sA1[NH], sA2[NH], sC0[NH], sC2[NH], sB[NH], sL[NH];
    int tid = threadIdx.x;
    if (tid < NH) {
        sA0[tid] = g_A[tid];
        sA1[tid] = g_A[NH + tid];
        sA2[tid] = g_A[2 * NH + tid];
        sC0[tid] = g_C[tid];
        float c1 = g_C[NH + tid];
        sC2[tid] = g_C[2 * NH + tid];
        sB[tid] = cb[tid] + c1;   // k=1 term always valid
        sL[tid] = lw[tid];
    }
    __syncthreads();
    int node = blockIdx.x * blockDim.x + tid;
    if (node >= n) return;

    float di = g_dinv[node];
    float self = di * di;
    float s[NBT];
#pragma unroll
    for (int j = 0; j < 12; j++) {
        float4 a = g_agg[node * 12 + j];
        float4 xv = g_xt[node * 12 + j];
        s[4 * j + 0] = fmaf(self, xv.x, a.x);
        s[4 * j + 1] = fmaf(self, xv.y, a.y);
        s[4 * j + 2] = fmaf(self, xv.z, a.z);
        s[4 * j + 3] = fmaf(self, xv.w, a.w);
    }
    float lbv = lb[0];
#pragma unroll
    for (int b = 0; b < NB; b++) {
        float acc = 0.f;
        for (int o = 0; o < NH; o++) {
            float A0 = sA0[o], A1 = sA1[o], A2 = sA2[o];
            float base = sB[o], C0 = sC0[o], C2 = sC2[o], L = sL[o];
#pragma unroll
            for (int t = 0; t < NT; t++) {
                float z = fmaf(A1, s[b * NT + t], base);
                if (t > 0) z = fmaf(A0, s[b * NT + t - 1], z + C0);
                if (t < NT - 1) z = fmaf(A2, s[b * NT + t + 1], z + C2);
                acc = fmaf(L, fmaxf(z, 0.f), acc);
            }
        }
        out[b * n + node] = fmaf(acc, 1.0f / (float)NT, lbv);
    }
}

// ---------------------------------------------------------------------------
extern "C" void kernel_launch(void* const* d_in, const int* in_sizes, int n_in,
                              void* d_out, int out_size) {
    const float* x  = (const float*)d_in[0];
    const void*  ei = d_in[1];
    const float* ew = (const float*)d_in[2];
    const float* gw = (const float*)d_in[3];
    const float* gb = (const float*)d_in[4];
    const float* cw = (const float*)d_in[5];
    const float* cb = (const float*)d_in[6];
    const float* lw = (const float*)d_in[7];
    const float* lb = (const float*)d_in[8];
    float* out = (float*)d_out;

    int N = in_sizes[0] / NBT;
    if (N > MAXN) N = MAXN;
    int E = in_sizes[2];

    int th = 256;
    k_init<<<(N * 12 + th - 1) / th, th>>>(N);
    k_detect<<<256, 256>>>((const unsigned*)ei, E);
    k_deg<<<(E + th - 1) / th, th>>>(ei, ew, E);
    k_rsqrt<<<(N + th - 1) / th, th>>>(N);
    k_trans<<<(N + 127) / 128, 128>>>(x, N);
    k_agg<<<(E + th - 1) / th, th>>>(ei, ew, E);
    k_prep<<<1, 96>>>(cw, gw, gb);
    k_out<<<(N + 127) / 128, 128>>>(cb, lw, lb, out, N);
}

// round 3
// speedup vs baseline: 2.2612x; 2.2612x over previous
#include <cuda_runtime.h>
#include <cstdint>

// STModel: GCN scatter-agg (scalar features x 48 time-batch slots) + folded
// temporal conv / relu / pool / linear epilogue.
//
//   deg[d]  = 1 + sum_{e: dst=d} w[e]          -> dinv = rsqrt(deg)
//   agg[n,bt] = sum_e norm_e * x[bt, src_e]  (+ dinv[n]^2 * x[bt,n] self-loop,
//                                             folded into epilogue)
//   A[o,k] = sum_i conv_w[o,i,k]*gcn_w[i];  C[o,k] = sum_i conv_w[o,i,k]*gcn_b[i]
//   z[o,t] = conv_b[o] + sum_{valid k} (A[o,k]*s[t+k-1] + C[o,k])
//   out[b,n] = lin_b + (1/12) * sum_{t,o} lin_w[o] * relu(z[o,t])
//
// R2: scalar atomicAdd -> red.global.add.v4.f32 (4x fewer LSU red ops);
//     fused rsqrt into transpose kernel; A/C fold moved into k_out.

#define MAXN 50000
#define NB 4
#define NT 12
#define NBT 48
#define NH 32

__device__ float  g_dinv[MAXN];        // deg accumulator, then dinv in place
__device__ float4 g_xt[MAXN * 12];     // x transposed: [N][48] as float4[N][12]
__device__ float4 g_agg[MAXN * 12];    // aggregate:    [N][48] as float4[N][12]
__device__ unsigned g_oddor;           // !=0 => edge_index int32; ==0 => int64

__device__ __forceinline__ void red_add_v4(float4* p, float4 v) {
    asm volatile("red.global.add.v4.f32 [%0], {%1,%2,%3,%4};"
                 :: "l"(p), "f"(v.x), "f"(v.y), "f"(v.z), "f"(v.w)
                 : "memory");
}

// ---------------------------------------------------------------------------
__global__ void k_init(int n) {
    int i = blockIdx.x * blockDim.x + threadIdx.x;
    if (i < n * 12) g_agg[i] = make_float4(0.f, 0.f, 0.f, 0.f);
    if (i < n) g_dinv[i] = 1.0f;       // self-loop weight preloaded into deg
    if (i == 0) g_oddor = 0u;
}

// Detect edge_index dtype: OR the odd 32-bit words of the first 2E words.
// int64 => those are high words of src indices (< 50000) => all zero.
__global__ void k_detect(const unsigned* __restrict__ w, int e) {
    unsigned acc = 0;
    for (int i = blockIdx.x * blockDim.x + threadIdx.x; i < e;
         i += gridDim.x * blockDim.x)
        acc |= w[2 * i + 1];
#pragma unroll
    for (int m = 16; m; m >>= 1) acc |= __shfl_xor_sync(0xffffffffu, acc, m);
    if ((threadIdx.x & 31) == 0 && acc) atomicOr(&g_oddor, acc);
}

__global__ void k_deg(const void* __restrict__ ei, const float* __restrict__ ew,
                      int e) {
    int i = blockIdx.x * blockDim.x + threadIdx.x;
    if (i >= e) return;
    int d;
    if (g_oddor) {
        d = ((const int*)ei)[e + i];
    } else {
        d = (int)((const long long*)ei)[e + i];
    }
    atomicAdd(&g_dinv[d], ew[i]);
}

// x [48, N] -> g_xt [N][48] (float4-packed); also finalize dinv = rsqrt(deg).
__global__ void k_trans(const float* __restrict__ x, int n) {
    int node = blockIdx.x * blockDim.x + threadIdx.x;
    if (node >= n) return;
    float dg = g_dinv[node];
    g_dinv[node] = (dg > 0.f) ? rsqrtf(dg) : 0.f;
    float v[NBT];
#pragma unroll
    for (int bt = 0; bt < NBT; bt++) v[bt] = x[bt * n + node];
#pragma unroll
    for (int j = 0; j < 12; j++)
        g_xt[node * 12 + j] =
            make_float4(v[4 * j], v[4 * j + 1], v[4 * j + 2], v[4 * j + 3]);
}

// One thread per edge: 12 x vector red into agg[dst].
__global__ void __launch_bounds__(256) k_agg(const void* __restrict__ ei,
                                             const float* __restrict__ ew,
                                             int e) {
    int i = blockIdx.x * blockDim.x + threadIdx.x;
    if (i >= e) return;
    int s, d;
    if (g_oddor) {
        const int* p = (const int*)ei;
        s = p[i];
        d = p[e + i];
    } else {
        const long long* p = (const long long*)ei;
        s = (int)p[i];
        d = (int)p[e + i];
    }
    float norm = g_dinv[s] * ew[i] * g_dinv[d];
    const float4* xp = &g_xt[s * 12];
    float4* ap = &g_agg[d * 12];
    float4 v[12];
#pragma unroll
    for (int j = 0; j < 12; j++) v[j] = xp[j];   // batch loads for MLP
#pragma unroll
    for (int j = 0; j < 12; j++) {
        float4 m = make_float4(v[j].x * norm, v[j].y * norm,
                               v[j].z * norm, v[j].w * norm);
        red_add_v4(ap + j, m);
    }
}

__global__ void __launch_bounds__(128) k_out(const float* __restrict__ cw,
                                             const float* __restrict__ gw,
                                             const float* __restrict__ gb,
                                             const float* __restrict__ cb,
                                             const float* __restrict__ lw,
                                             const float* __restrict__ lb,
                                             float* __restrict__ out, int n) {
    __shared__ float sA0[NH], sA1[NH], sA2[NH], sC0[NH], sC2[NH], sB[NH], sL[NH];
    int tid = threadIdx.x;
    // Per-block fold of conv_w with gcn_w/gcn_b (96 threads, 32 fmas each).
    if (tid < 96) {
        int o = tid / 3, k = tid % 3;
        float a = 0.f, c = 0.f;
#pragma unroll
        for (int i = 0; i < NH; i++) {
            float w = cw[o * (NH * 3) + i * 3 + k];
            a = fmaf(w, gw[i], a);
            c = fmaf(w, gb[i], c);
        }
        if (k == 0) { sA0[o] = a; sC0[o] = c; }
        else if (k == 1) { sA1[o] = a; sB[o] = cb[o] + c; sL[o] = lw[o]; }
        else { sA2[o] = a; sC2[o] = c; }
    }
    __syncthreads();
    int node = blockIdx.x * blockDim.x + tid;
    if (node >= n) return;

    float di = g_dinv[node];
    float self = di * di;
    float s[NBT];
#pragma unroll
    for (int j = 0; j < 12; j++) {
        float4 a = g_agg[node * 12 + j];
        float4 xv = g_xt[node * 12 + j];
        s[4 * j + 0] = fmaf(self, xv.x, a.x);
        s[4 * j + 1] = fmaf(self, xv.y, a.y);
        s[4 * j + 2] = fmaf(self, xv.z, a.z);
        s[4 * j + 3] = fmaf(self, xv.w, a.w);
    }
    float lbv = lb[0];
#pragma unroll
    for (int b = 0; b < NB; b++) {
        float acc = 0.f;
        for (int o = 0; o < NH; o++) {
            float A0 = sA0[o], A1 = sA1[o], A2 = sA2[o];
            float base = sB[o], C0 = sC0[o], C2 = sC2[o], L = sL[o];
#pragma unroll
            for (int t = 0; t < NT; t++) {
                float z = fmaf(A1, s[b * NT + t], base);
                if (t > 0) z = fmaf(A0, s[b * NT + t - 1], z + C0);
                if (t < NT - 1) z = fmaf(A2, s[b * NT + t + 1], z + C2);
                acc = fmaf(L, fmaxf(z, 0.f), acc);
            }
        }
        out[b * n + node] = fmaf(acc, 1.0f / (float)NT, lbv);
    }
}

// ---------------------------------------------------------------------------
extern "C" void kernel_launch(void* const* d_in, const int* in_sizes, int n_in,
                              void* d_out, int out_size) {
    const float* x  = (const float*)d_in[0];
    const void*  ei = d_in[1];
    const float* ew = (const float*)d_in[2];
    const float* gw = (const float*)d_in[3];
    const float* gb = (const float*)d_in[4];
    const float* cw = (const float*)d_in[5];
    const float* cb = (const float*)d_in[6];
    const float* lw = (const float*)d_in[7];
    const float* lb = (const float*)d_in[8];
    float* out = (float*)d_out;

    int N = in_sizes[0] / NBT;
    if (N > MAXN) N = MAXN;
    int E = in_sizes[2];

    int th = 256;
    k_init<<<(N * 12 + th - 1) / th, th>>>(N);
    k_detect<<<256, 256>>>((const unsigned*)ei, E);
    k_deg<<<(E + th - 1) / th, th>>>(ei, ew, E);
    k_trans<<<(N + 127) / 128, 128>>>(x, N);
    k_agg<<<(E + th - 1) / th, th>>>(ei, ew, E);
    k_out<<<(N + 127) / 128, 128>>>(cw, gw, gb, cb, lw, lb, out, N);
}